// round 13
// baseline (speedup 1.0000x reference)
#include <cuda_runtime.h>
#include <cuda_bf16.h>
#include <math.h>
#include <stdint.h>

// Fixed problem shape (from setup_inputs): N=100000, E=1600000, F_IN=128, H=C=64
#define NNODES 100000
#define HD 64
#define MSGMAX 1800000   // E + N with headroom

// Scratch (allocation-free: __device__ globals)
__device__ int    g_cnt[NNODES];            // per-dst message count (incl. self-loop)
__device__ int    g_off[NNODES + 1];        // CSR offsets
__device__ int    g_cur[NNODES];            // placement cursors
__device__ int    g_bsum[512];              // block sums for scan
__device__ int    g_boff[512];              // block offsets for scan
__device__ float2 g_rec[MSGMAX];            // per-message {src_bits, norm}
__device__ uint4  g_h[NNODES * 8];          // GEMM output in bf16 (64 bf16 = 8 uint4/row)
__device__ float  g_agg[NNODES * HD];       // layer-1 aggregate (fp32)
__device__ int    g_is64;                   // edge_index dtype flag

__device__ __forceinline__ long long load_edge(const void* ei, long long pos) {
    if (g_is64) return ((const long long*)ei)[pos];
    return (long long)((const int*)ei)[pos];
}

// ---------------------------------------------------------------------------
// init: cnt = 1 (self loop), detect index width
// ---------------------------------------------------------------------------
__global__ void k_init(const void* ei, int N) {
    int i = blockIdx.x * 256 + threadIdx.x;
    if (i < N) g_cnt[i] = 1;
    if (i == 0) {
        const unsigned long long* p = (const unsigned long long*)ei;
        int ok = 1;
        #pragma unroll 4
        for (int j = 0; j < 64; j++)
            if (p[j] >= (unsigned long long)N) ok = 0;
        g_is64 = ok;
    }
}

// ---------------------------------------------------------------------------
// degree count over dst
// ---------------------------------------------------------------------------
__global__ void k_count(const void* ei, long long E) {
    long long e = (long long)blockIdx.x * 256 + threadIdx.x;
    if (e < E) {
        int d = (int)load_edge(ei, E + e);
        atomicAdd(&g_cnt[d], 1);
    }
}

// ---------------------------------------------------------------------------
// 3-phase exclusive scan of g_cnt -> g_off  (R5-proven)
// ---------------------------------------------------------------------------
__global__ void k_scan1(int N) {
    __shared__ int s[256];
    int i = blockIdx.x * 256 + threadIdx.x;
    int v = (i < N) ? g_cnt[i] : 0;
    s[threadIdx.x] = v;
    __syncthreads();
    #pragma unroll
    for (int o = 128; o > 0; o >>= 1) {
        if (threadIdx.x < o) s[threadIdx.x] += s[threadIdx.x + o];
        __syncthreads();
    }
    if (threadIdx.x == 0) g_bsum[blockIdx.x] = s[0];
}

__global__ void k_scan2(int nb) {
    __shared__ int wsum[16];
    int t = threadIdx.x;
    int lane = t & 31;
    int w = t >> 5;
    int v = (t < nb) ? g_bsum[t] : 0;
    int x = v;
    #pragma unroll
    for (int o = 1; o < 32; o <<= 1) {
        int y = __shfl_up_sync(0xffffffffu, x, o);
        if (lane >= o) x += y;
    }
    if (lane == 31) wsum[w] = x;
    __syncthreads();
    if (w == 0) {
        int ws = (lane < 16) ? wsum[lane] : 0;
        #pragma unroll
        for (int o = 1; o < 16; o <<= 1) {
            int y = __shfl_up_sync(0xffffffffu, ws, o);
            if (lane >= o) ws += y;
        }
        if (lane < 16) wsum[lane] = ws;
    }
    __syncthreads();
    int base = (w > 0) ? wsum[w - 1] : 0;
    if (t < nb) g_boff[t] = base + x - v;
}

__global__ void k_scan3(int N) {
    __shared__ int s[256];
    int i = blockIdx.x * 256 + threadIdx.x;
    int v = (i < N) ? g_cnt[i] : 0;
    s[threadIdx.x] = v;
    __syncthreads();
    #pragma unroll
    for (int o = 1; o < 256; o <<= 1) {
        int tv = (threadIdx.x >= o) ? s[threadIdx.x - o] : 0;
        __syncthreads();
        s[threadIdx.x] += tv;
        __syncthreads();
    }
    if (i < N) {
        int off = g_boff[blockIdx.x] + s[threadIdx.x] - v;
        g_off[i] = off;
        g_cur[i] = off;
        if (i == N - 1) g_off[N] = off + v;
    }
}

// ---------------------------------------------------------------------------
// place: bucket message records {src, rsqrt(deg_s*deg_d)} by dst
// ---------------------------------------------------------------------------
__global__ void k_place(const void* ei, long long E, int N) {
    long long e = (long long)blockIdx.x * 256 + threadIdx.x;
    long long M = E + (long long)N;
    if (e >= M) return;
    int s, d;
    if (e < E) {
        s = (int)load_edge(ei, e);
        d = (int)load_edge(ei, E + e);
    } else {
        s = d = (int)(e - E);
    }
    float nrm = rsqrtf((float)(g_cnt[s] * g_cnt[d]));
    int pos = atomicAdd(&g_cur[d], 1);
    g_rec[pos] = make_float2(__int_as_float(s), nrm);
}

// ---------------------------------------------------------------------------
// GEMM1 via mma.sync bf16 HMMA (proven R11).
// CTA: 128 rows x 64 cols x K=128. 8 warps, warp tile m16 x n64.
// ---------------------------------------------------------------------------
#define G1_XSTRIDE 136                    // bf16 units per X smem row
#define G1_XS_BYTES (128 * G1_XSTRIDE * 2)   // 34816
#define G1_WF_OFF   G1_XS_BYTES
#define G1_SMEM_TOT (G1_XS_BYTES + 8 * 8 * 32 * 8)   // + 16384 = 51200

__global__ __launch_bounds__(256)
void k_gemm1_mma(const float* __restrict__ X, const float* __restrict__ W,
                 unsigned* __restrict__ out, int N) {
    extern __shared__ char smem[];
    __nv_bfloat16* Xs = (__nv_bfloat16*)smem;
    uint2* Wf = (uint2*)(smem + G1_WF_OFF);

    int tid = threadIdx.x;
    int wid = tid >> 5, lane = tid & 31;
    int tig = lane & 3, gid = lane >> 2;
    int row0 = blockIdx.x * 128;

    // Pack W fragments: Wf[(ks*8+nt)*32 + lane] = {bf16x2(b0,b1), bf16x2(b2,b3)}
    for (int idx = tid; idx < 2048; idx += 256) {
        int l = idx & 31;
        int nt = (idx >> 5) & 7;
        int ks = idx >> 8;
        int lt = l & 3, lg = l >> 2;
        int k0 = ks * 16 + lt * 2;
        int n  = nt * 8 + lg;
        float b0 = W[(long long)k0 * 64 + n];
        float b1 = W[(long long)(k0 + 1) * 64 + n];
        float b2 = W[(long long)(k0 + 8) * 64 + n];
        float b3 = W[(long long)(k0 + 9) * 64 + n];
        __nv_bfloat162 p0 = __float22bfloat162_rn(make_float2(b0, b1));
        __nv_bfloat162 p1 = __float22bfloat162_rn(make_float2(b2, b3));
        Wf[idx] = make_uint2(*(unsigned*)&p0, *(unsigned*)&p1);
    }

    // X tile fp32 -> bf16 smem (coalesced float4 reads)
    for (int idx = tid; idx < 128 * 32; idx += 256) {
        int r  = idx >> 5;
        int c4 = idx & 31;
        int gr = row0 + r;
        float4 v = make_float4(0.f, 0.f, 0.f, 0.f);
        if (gr < N) v = *(const float4*)(X + (long long)gr * 128 + c4 * 4);
        __nv_bfloat162 p0 = __float22bfloat162_rn(make_float2(v.x, v.y));
        __nv_bfloat162 p1 = __float22bfloat162_rn(make_float2(v.z, v.w));
        *(uint2*)((char*)Xs + ((long long)r * G1_XSTRIDE + c4 * 4) * 2) =
            make_uint2(*(unsigned*)&p0, *(unsigned*)&p1);
    }
    __syncthreads();

    float acc[8][4];
    #pragma unroll
    for (int nt = 0; nt < 8; nt++)
        #pragma unroll
        for (int q = 0; q < 4; q++) acc[nt][q] = 0.f;

    int rw = wid * 16;
    const char* XsB = (const char*)Xs;

    #pragma unroll
    for (int ks = 0; ks < 8; ks++) {
        int cbase = ks * 16 + tig * 2;
        unsigned A0 = *(const unsigned*)(XsB + ((rw + gid)     * G1_XSTRIDE + cbase)     * 2);
        unsigned A1 = *(const unsigned*)(XsB + ((rw + gid + 8) * G1_XSTRIDE + cbase)     * 2);
        unsigned A2 = *(const unsigned*)(XsB + ((rw + gid)     * G1_XSTRIDE + cbase + 8) * 2);
        unsigned A3 = *(const unsigned*)(XsB + ((rw + gid + 8) * G1_XSTRIDE + cbase + 8) * 2);
        #pragma unroll
        for (int nt = 0; nt < 8; nt++) {
            uint2 bb = Wf[(ks * 8 + nt) * 32 + lane];
            asm volatile(
                "mma.sync.aligned.m16n8k16.row.col.f32.bf16.bf16.f32 "
                "{%0,%1,%2,%3}, {%4,%5,%6,%7}, {%8,%9}, {%0,%1,%2,%3};"
                : "+f"(acc[nt][0]), "+f"(acc[nt][1]),
                  "+f"(acc[nt][2]), "+f"(acc[nt][3])
                : "r"(A0), "r"(A1), "r"(A2), "r"(A3),
                  "r"(bb.x), "r"(bb.y));
        }
    }

    int gr0 = row0 + rw + gid;
    int gr1 = gr0 + 8;
    #pragma unroll
    for (int nt = 0; nt < 8; nt++) {
        int cw = nt * 4 + tig;
        if (gr0 < N) {
            __nv_bfloat162 p = __float22bfloat162_rn(
                make_float2(acc[nt][0], acc[nt][1]));
            out[(long long)gr0 * 32 + cw] = *(unsigned*)&p;
        }
        if (gr1 < N) {
            __nv_bfloat162 p = __float22bfloat162_rn(
                make_float2(acc[nt][2], acc[nt][3]));
            out[(long long)gr1 * 32 + cw] = *(unsigned*)&p;
        }
    }
}

// ---------------------------------------------------------------------------
// GEMM2 via mma.sync bf16 HMMA (proven R12): relu(agg+b1) @ W2 -> bf16.
// ---------------------------------------------------------------------------
#define G2_XSTRIDE 72

__global__ __launch_bounds__(256)
void k_gemm2_mma(const float* __restrict__ X, const float* __restrict__ W,
                 const float* __restrict__ bias, unsigned* __restrict__ out,
                 int N) {
    __shared__ __nv_bfloat16 Xs[128 * G2_XSTRIDE];   // 18432 B
    __shared__ uint2 Wf[4 * 8 * 32];                 // 8192 B

    int tid = threadIdx.x;
    int wid = tid >> 5, lane = tid & 31;
    int tig = lane & 3, gid = lane >> 2;
    int row0 = blockIdx.x * 128;

    for (int idx = tid; idx < 1024; idx += 256) {
        int l = idx & 31;
        int nt = (idx >> 5) & 7;
        int ks = idx >> 8;
        int lt = l & 3, lg = l >> 2;
        int k0 = ks * 16 + lt * 2;
        int n  = nt * 8 + lg;
        float b0 = W[(long long)k0 * 64 + n];
        float b1 = W[(long long)(k0 + 1) * 64 + n];
        float b2 = W[(long long)(k0 + 8) * 64 + n];
        float b3 = W[(long long)(k0 + 9) * 64 + n];
        __nv_bfloat162 p0 = __float22bfloat162_rn(make_float2(b0, b1));
        __nv_bfloat162 p1 = __float22bfloat162_rn(make_float2(b2, b3));
        Wf[idx] = make_uint2(*(unsigned*)&p0, *(unsigned*)&p1);
    }

    for (int idx = tid; idx < 128 * 16; idx += 256) {
        int r  = idx >> 4;
        int c4 = idx & 15;
        int gr = row0 + r;
        float4 v = make_float4(0.f, 0.f, 0.f, 0.f);
        if (gr < N) {
            v = *(const float4*)(X + (long long)gr * 64 + c4 * 4);
            float4 bv = __ldg((const float4*)bias + c4);
            v.x = fmaxf(v.x + bv.x, 0.f);
            v.y = fmaxf(v.y + bv.y, 0.f);
            v.z = fmaxf(v.z + bv.z, 0.f);
            v.w = fmaxf(v.w + bv.w, 0.f);
        }
        __nv_bfloat162 p0 = __float22bfloat162_rn(make_float2(v.x, v.y));
        __nv_bfloat162 p1 = __float22bfloat162_rn(make_float2(v.z, v.w));
        *(uint2*)((char*)Xs + ((long long)r * G2_XSTRIDE + c4 * 4) * 2) =
            make_uint2(*(unsigned*)&p0, *(unsigned*)&p1);
    }
    __syncthreads();

    float acc[8][4];
    #pragma unroll
    for (int nt = 0; nt < 8; nt++)
        #pragma unroll
        for (int q = 0; q < 4; q++) acc[nt][q] = 0.f;

    int rw = wid * 16;
    const char* XsB = (const char*)Xs;

    #pragma unroll
    for (int ks = 0; ks < 4; ks++) {
        int cbase = ks * 16 + tig * 2;
        unsigned A0 = *(const unsigned*)(XsB + ((rw + gid)     * G2_XSTRIDE + cbase)     * 2);
        unsigned A1 = *(const unsigned*)(XsB + ((rw + gid + 8) * G2_XSTRIDE + cbase)     * 2);
        unsigned A2 = *(const unsigned*)(XsB + ((rw + gid)     * G2_XSTRIDE + cbase + 8) * 2);
        unsigned A3 = *(const unsigned*)(XsB + ((rw + gid + 8) * G2_XSTRIDE + cbase + 8) * 2);
        #pragma unroll
        for (int nt = 0; nt < 8; nt++) {
            uint2 bb = Wf[(ks * 8 + nt) * 32 + lane];
            asm volatile(
                "mma.sync.aligned.m16n8k16.row.col.f32.bf16.bf16.f32 "
                "{%0,%1,%2,%3}, {%4,%5,%6,%7}, {%8,%9}, {%0,%1,%2,%3};"
                : "+f"(acc[nt][0]), "+f"(acc[nt][1]),
                  "+f"(acc[nt][2]), "+f"(acc[nt][3])
                : "r"(A0), "r"(A1), "r"(A2), "r"(A3),
                  "r"(bb.x), "r"(bb.y));
        }
    }

    int gr0 = row0 + rw + gid;
    int gr1 = gr0 + 8;
    #pragma unroll
    for (int nt = 0; nt < 8; nt++) {
        int cw = nt * 4 + tig;
        if (gr0 < N) {
            __nv_bfloat162 p = __float22bfloat162_rn(
                make_float2(acc[nt][0], acc[nt][1]));
            out[(long long)gr0 * 32 + cw] = *(unsigned*)&p;
        }
        if (gr1 < N) {
            __nv_bfloat162 p = __float22bfloat162_rn(
                make_float2(acc[nt][2], acc[nt][3]));
            out[(long long)gr1 * 32 + cw] = *(unsigned*)&p;
        }
    }
}

// ---------------------------------------------------------------------------
// Aggregate from bf16 h — SOFTWARE-PIPELINED gather (depth-2 record prefetch).
// The record for iteration i is loaded at i-2, so the rec->gather dependent
// chain is broken: consecutive gathers are independent (coupled only through
// the FADD accumulator) and 2-4 stay in flight per 8-lane group.
// EPI==1: fuse +b2 and log_softmax.
// ---------------------------------------------------------------------------
template <int EPI>
__global__ void k_agg(const uint4* __restrict__ h, float* __restrict__ out,
                      const float* __restrict__ bias, int N) {
    int node = blockIdx.x * 8 + (threadIdx.x >> 5);
    if (node >= N) return;
    int lane = threadIdx.x & 31;
    int grp = lane >> 3;
    int gl  = lane & 7;
    int beg = g_off[node];
    int end = g_off[node + 1];

    float2 acc[4];
    #pragma unroll
    for (int i = 0; i < 4; i++) acc[i] = make_float2(0.f, 0.f);

    int j = beg + grp;
    float2 r0 = (j < end)     ? __ldg(&g_rec[j])     : make_float2(__int_as_float(0), 0.f);
    float2 r1 = (j + 4 < end) ? __ldg(&g_rec[j + 4]) : make_float2(__int_as_float(0), 0.f);

    #pragma unroll 2
    for (; j < end; j += 4) {
        float2 rn = (j + 8 < end) ? __ldg(&g_rec[j + 8])
                                  : make_float2(__int_as_float(0), 0.f);
        int s = __float_as_int(r0.x);
        float nrm = r0.y;
        uint4 v = __ldg(h + (long long)s * 8 + gl);
        float2 f;
        f = __bfloat1622float2(*(__nv_bfloat162*)&v.x);
        acc[0].x += f.x * nrm; acc[0].y += f.y * nrm;
        f = __bfloat1622float2(*(__nv_bfloat162*)&v.y);
        acc[1].x += f.x * nrm; acc[1].y += f.y * nrm;
        f = __bfloat1622float2(*(__nv_bfloat162*)&v.z);
        acc[2].x += f.x * nrm; acc[2].y += f.y * nrm;
        f = __bfloat1622float2(*(__nv_bfloat162*)&v.w);
        acc[3].x += f.x * nrm; acc[3].y += f.y * nrm;
        r0 = r1;
        r1 = rn;
    }
    #pragma unroll
    for (int i = 0; i < 4; i++) {
        acc[i].x += __shfl_xor_sync(0xffffffffu, acc[i].x, 8);
        acc[i].y += __shfl_xor_sync(0xffffffffu, acc[i].y, 8);
        acc[i].x += __shfl_xor_sync(0xffffffffu, acc[i].x, 16);
        acc[i].y += __shfl_xor_sync(0xffffffffu, acc[i].y, 16);
    }

    if (EPI == 0) {
        if (lane < 8) {
            float4* op = (float4*)(out + (long long)node * 64 + gl * 8);
            op[0] = make_float4(acc[0].x, acc[0].y, acc[1].x, acc[1].y);
            op[1] = make_float4(acc[2].x, acc[2].y, acc[3].x, acc[3].y);
        }
    } else {
        const float4* bp = (const float4*)(bias + gl * 8);
        float4 b0 = bp[0], b1 = bp[1];
        acc[0].x += b0.x; acc[0].y += b0.y; acc[1].x += b0.z; acc[1].y += b0.w;
        acc[2].x += b1.x; acc[2].y += b1.y; acc[3].x += b1.z; acc[3].y += b1.w;
        float m = fmaxf(fmaxf(fmaxf(acc[0].x, acc[0].y), fmaxf(acc[1].x, acc[1].y)),
                        fmaxf(fmaxf(acc[2].x, acc[2].y), fmaxf(acc[3].x, acc[3].y)));
        #pragma unroll
        for (int o = 1; o < 8; o <<= 1)
            m = fmaxf(m, __shfl_xor_sync(0xffffffffu, m, o));
        float s = expf(acc[0].x - m) + expf(acc[0].y - m)
                + expf(acc[1].x - m) + expf(acc[1].y - m)
                + expf(acc[2].x - m) + expf(acc[2].y - m)
                + expf(acc[3].x - m) + expf(acc[3].y - m);
        #pragma unroll
        for (int o = 1; o < 8; o <<= 1)
            s += __shfl_xor_sync(0xffffffffu, s, o);
        float lse = m + logf(s);
        if (lane < 8) {
            float4* op = (float4*)(out + (long long)node * 64 + gl * 8);
            op[0] = make_float4(acc[0].x - lse, acc[0].y - lse,
                                acc[1].x - lse, acc[1].y - lse);
            op[1] = make_float4(acc[2].x - lse, acc[2].y - lse,
                                acc[3].x - lse, acc[3].y - lse);
        }
    }
}

// ---------------------------------------------------------------------------
extern "C" void kernel_launch(void* const* d_in, const int* in_sizes, int n_in,
                              void* d_out, int out_size) {
    const float* x  = (const float*)d_in[0];
    const void*  ei = d_in[1];
    const float* W1 = (const float*)d_in[2];
    const float* b1 = (const float*)d_in[3];
    const float* W2 = (const float*)d_in[4];
    const float* b2 = (const float*)d_in[5];
    float* out = (float*)d_out;

    int N = in_sizes[0] / 128;                 // 100000
    long long E = (long long)in_sizes[1] / 2;  // 1600000
    long long M = E + (long long)N;

    static cudaStream_t s2 = nullptr;
    static cudaEvent_t evFork = nullptr, evJoin = nullptr;
    if (!s2) {
        cudaStreamCreateWithFlags(&s2, cudaStreamNonBlocking);
        cudaEventCreateWithFlags(&evFork, cudaEventDisableTiming);
        cudaEventCreateWithFlags(&evJoin, cudaEventDisableTiming);
        cudaFuncSetAttribute(k_gemm1_mma,
                             cudaFuncAttributeMaxDynamicSharedMemorySize,
                             G1_SMEM_TOT);
    }

    uint4* ph;
    float* pagg;
    cudaGetSymbolAddress((void**)&ph, g_h);
    cudaGetSymbolAddress((void**)&pagg, g_agg);

    int bN    = (N + 255) / 256;
    int bDeg  = (int)((E + 255) / 256);
    int bMsg  = (int)((M + 255) / 256);
    int bGemm = (N + 127) / 128;
    int bAgg  = (N + 7) / 8;

    // Fork: HMMA GEMM1 (x,W1 only) on s2, concurrent with CSR prep.
    cudaEventRecord(evFork, 0);
    cudaStreamWaitEvent(s2, evFork, 0);
    k_gemm1_mma<<<bGemm, 256, G1_SMEM_TOT, s2>>>(x, W1, (unsigned*)ph, N);
    cudaEventRecord(evJoin, s2);

    k_init<<<bN, 256>>>(ei, N);
    k_count<<<bDeg, 256>>>(ei, E);
    k_scan1<<<bN, 256>>>(N);
    k_scan2<<<1, 512>>>(bN);
    k_scan3<<<bN, 256>>>(N);
    k_place<<<bMsg, 256>>>(ei, E, N);

    // Join: aggregation needs both g_h (s2) and g_rec (default)
    cudaStreamWaitEvent(0, evJoin, 0);

    // layer 1 aggregate (fp32 out)
    k_agg<0><<<bAgg, 256>>>(ph, pagg, nullptr, N);

    // layer 2: h2 = relu(agg1 + b1) @ W2 via HMMA (bf16 out, overwrites g_h)
    k_gemm2_mma<<<bGemm, 256>>>(pagg, W2, b1, (unsigned*)ph, N);

    // final aggregate + b2 + log_softmax
    k_agg<1><<<bAgg, 256>>>(ph, out, b2, N);
}

// round 14
// speedup vs baseline: 1.0070x; 1.0070x over previous
#include <cuda_runtime.h>
#include <cuda_bf16.h>
#include <math.h>
#include <stdint.h>

// Fixed problem shape (from setup_inputs): N=100000, E=1600000, F_IN=128, H=C=64
#define NNODES 100000
#define HD 64
#define MSGMAX 1800000   // E + N with headroom

// Scratch (allocation-free: __device__ globals)
__device__ int    g_cnt[NNODES];            // per-dst message count (incl. self-loop)
__device__ int    g_off[NNODES + 1];        // CSR offsets
__device__ int    g_cur[NNODES];            // placement cursors
__device__ int    g_bsum[512];              // block sums for scan
__device__ float2 g_rec[MSGMAX];            // per-message {src_bits, norm}
__device__ uint4  g_h[NNODES * 8];          // GEMM output in bf16 (64 bf16 = 8 uint4/row)
__device__ float  g_agg[NNODES * HD];       // layer-1 aggregate (fp32)
__device__ int    g_is64;                   // edge_index dtype flag

__device__ __forceinline__ long long load_edge(const void* ei, long long pos) {
    if (g_is64) return ((const long long*)ei)[pos];
    return (long long)((const int*)ei)[pos];
}

// ---------------------------------------------------------------------------
// init: cnt = 1 (self loop), detect index width
// ---------------------------------------------------------------------------
__global__ void k_init(const void* ei, int N) {
    int i = blockIdx.x * 256 + threadIdx.x;
    if (i < N) g_cnt[i] = 1;
    if (i == 0) {
        const unsigned long long* p = (const unsigned long long*)ei;
        int ok = 1;
        #pragma unroll 4
        for (int j = 0; j < 64; j++)
            if (p[j] >= (unsigned long long)N) ok = 0;
        g_is64 = ok;
    }
}

// ---------------------------------------------------------------------------
// degree count over dst
// ---------------------------------------------------------------------------
__global__ void k_count(const void* ei, long long E) {
    long long e = (long long)blockIdx.x * 256 + threadIdx.x;
    if (e < E) {
        int d = (int)load_edge(ei, E + e);
        atomicAdd(&g_cnt[d], 1);
    }
}

// ---------------------------------------------------------------------------
// scan stage (2 kernels, shuffle-based):
//  k_scan1: block reduce of 256 counts -> g_bsum[b]
//  k_scan23: per-block offset (sum of g_bsum[0..b)) + exclusive block scan
// ---------------------------------------------------------------------------
__global__ void k_scan1(int N) {
    __shared__ int ws[8];
    int i = blockIdx.x * 256 + threadIdx.x;
    int lane = threadIdx.x & 31;
    int w = threadIdx.x >> 5;
    int v = (i < N) ? g_cnt[i] : 0;
    int s = v;
    #pragma unroll
    for (int o = 16; o > 0; o >>= 1) s += __shfl_xor_sync(0xffffffffu, s, o);
    if (lane == 0) ws[w] = s;
    __syncthreads();
    if (threadIdx.x < 8) {
        int t = ws[threadIdx.x];
        #pragma unroll
        for (int o = 4; o > 0; o >>= 1) t += __shfl_xor_sync(0xffu, t, o);
        if (threadIdx.x == 0) g_bsum[blockIdx.x] = t;
    }
}

__global__ void k_scan23(int N, int nb) {
    __shared__ int wsum[8];
    __shared__ int bws[8];
    int b = blockIdx.x, tid = threadIdx.x;
    int lane = tid & 31;
    int w = tid >> 5;
    int i = b * 256 + tid;

    // block offset: sum of g_bsum[j] for j < b (<=2 elements per thread)
    int part = 0;
    for (int j = tid; j < b; j += 256) part += g_bsum[j];
    #pragma unroll
    for (int o = 16; o > 0; o >>= 1) part += __shfl_xor_sync(0xffffffffu, part, o);
    if (lane == 0) bws[w] = part;

    // exclusive scan of this block's 256 counts (shuffle)
    int v = (i < N) ? g_cnt[i] : 0;
    int x = v;
    #pragma unroll
    for (int o = 1; o < 32; o <<= 1) {
        int y = __shfl_up_sync(0xffffffffu, x, o);
        if (lane >= o) x += y;
    }
    if (lane == 31) wsum[w] = x;
    __syncthreads();

    int blockoff = 0;
    {
        // reduce bws[0..7] (uniform over threads)
        #pragma unroll
        for (int q = 0; q < 8; q++) blockoff += bws[q];
    }
    int wbase = 0;
    #pragma unroll
    for (int q = 0; q < 8; q++) wbase += (q < w) ? wsum[q] : 0;

    if (i < N) {
        int off = blockoff + wbase + x - v;   // exclusive
        g_off[i] = off;
        g_cur[i] = off;
        if (i == N - 1) g_off[N] = off + v;
    }
}

// ---------------------------------------------------------------------------
// place: bucket message records {src, rsqrt(deg_s*deg_d)} by dst
// ---------------------------------------------------------------------------
__global__ void k_place(const void* ei, long long E, int N) {
    long long e = (long long)blockIdx.x * 256 + threadIdx.x;
    long long M = E + (long long)N;
    if (e >= M) return;
    int s, d;
    if (e < E) {
        s = (int)load_edge(ei, e);
        d = (int)load_edge(ei, E + e);
    } else {
        s = d = (int)(e - E);
    }
    float nrm = rsqrtf((float)(g_cnt[s] * g_cnt[d]));
    int pos = atomicAdd(&g_cur[d], 1);
    g_rec[pos] = make_float2(__int_as_float(s), nrm);
}

// ---------------------------------------------------------------------------
// GEMM1 via mma.sync bf16 HMMA (proven R11).
// CTA: 128 rows x 64 cols x K=128. 8 warps, warp tile m16 x n64.
// ---------------------------------------------------------------------------
#define G1_XSTRIDE 136                    // bf16 units per X smem row
#define G1_XS_BYTES (128 * G1_XSTRIDE * 2)   // 34816
#define G1_WF_OFF   G1_XS_BYTES
#define G1_SMEM_TOT (G1_XS_BYTES + 8 * 8 * 32 * 8)   // + 16384 = 51200

__global__ __launch_bounds__(256)
void k_gemm1_mma(const float* __restrict__ X, const float* __restrict__ W,
                 unsigned* __restrict__ out, int N) {
    extern __shared__ char smem[];
    __nv_bfloat16* Xs = (__nv_bfloat16*)smem;
    uint2* Wf = (uint2*)(smem + G1_WF_OFF);

    int tid = threadIdx.x;
    int wid = tid >> 5, lane = tid & 31;
    int tig = lane & 3, gid = lane >> 2;
    int row0 = blockIdx.x * 128;

    // Pack W fragments: Wf[(ks*8+nt)*32 + lane] = {bf16x2(b0,b1), bf16x2(b2,b3)}
    for (int idx = tid; idx < 2048; idx += 256) {
        int l = idx & 31;
        int nt = (idx >> 5) & 7;
        int ks = idx >> 8;
        int lt = l & 3, lg = l >> 2;
        int k0 = ks * 16 + lt * 2;
        int n  = nt * 8 + lg;
        float b0 = W[(long long)k0 * 64 + n];
        float b1 = W[(long long)(k0 + 1) * 64 + n];
        float b2 = W[(long long)(k0 + 8) * 64 + n];
        float b3 = W[(long long)(k0 + 9) * 64 + n];
        __nv_bfloat162 p0 = __float22bfloat162_rn(make_float2(b0, b1));
        __nv_bfloat162 p1 = __float22bfloat162_rn(make_float2(b2, b3));
        Wf[idx] = make_uint2(*(unsigned*)&p0, *(unsigned*)&p1);
    }

    // X tile fp32 -> bf16 smem (coalesced float4 reads)
    for (int idx = tid; idx < 128 * 32; idx += 256) {
        int r  = idx >> 5;
        int c4 = idx & 31;
        int gr = row0 + r;
        float4 v = make_float4(0.f, 0.f, 0.f, 0.f);
        if (gr < N) v = *(const float4*)(X + (long long)gr * 128 + c4 * 4);
        __nv_bfloat162 p0 = __float22bfloat162_rn(make_float2(v.x, v.y));
        __nv_bfloat162 p1 = __float22bfloat162_rn(make_float2(v.z, v.w));
        *(uint2*)((char*)Xs + ((long long)r * G1_XSTRIDE + c4 * 4) * 2) =
            make_uint2(*(unsigned*)&p0, *(unsigned*)&p1);
    }
    __syncthreads();

    float acc[8][4];
    #pragma unroll
    for (int nt = 0; nt < 8; nt++)
        #pragma unroll
        for (int q = 0; q < 4; q++) acc[nt][q] = 0.f;

    int rw = wid * 16;
    const char* XsB = (const char*)Xs;

    #pragma unroll
    for (int ks = 0; ks < 8; ks++) {
        int cbase = ks * 16 + tig * 2;
        unsigned A0 = *(const unsigned*)(XsB + ((rw + gid)     * G1_XSTRIDE + cbase)     * 2);
        unsigned A1 = *(const unsigned*)(XsB + ((rw + gid + 8) * G1_XSTRIDE + cbase)     * 2);
        unsigned A2 = *(const unsigned*)(XsB + ((rw + gid)     * G1_XSTRIDE + cbase + 8) * 2);
        unsigned A3 = *(const unsigned*)(XsB + ((rw + gid + 8) * G1_XSTRIDE + cbase + 8) * 2);
        #pragma unroll
        for (int nt = 0; nt < 8; nt++) {
            uint2 bb = Wf[(ks * 8 + nt) * 32 + lane];
            asm volatile(
                "mma.sync.aligned.m16n8k16.row.col.f32.bf16.bf16.f32 "
                "{%0,%1,%2,%3}, {%4,%5,%6,%7}, {%8,%9}, {%0,%1,%2,%3};"
                : "+f"(acc[nt][0]), "+f"(acc[nt][1]),
                  "+f"(acc[nt][2]), "+f"(acc[nt][3])
                : "r"(A0), "r"(A1), "r"(A2), "r"(A3),
                  "r"(bb.x), "r"(bb.y));
        }
    }

    int gr0 = row0 + rw + gid;
    int gr1 = gr0 + 8;
    #pragma unroll
    for (int nt = 0; nt < 8; nt++) {
        int cw = nt * 4 + tig;
        if (gr0 < N) {
            __nv_bfloat162 p = __float22bfloat162_rn(
                make_float2(acc[nt][0], acc[nt][1]));
            out[(long long)gr0 * 32 + cw] = *(unsigned*)&p;
        }
        if (gr1 < N) {
            __nv_bfloat162 p = __float22bfloat162_rn(
                make_float2(acc[nt][2], acc[nt][3]));
            out[(long long)gr1 * 32 + cw] = *(unsigned*)&p;
        }
    }
}

// ---------------------------------------------------------------------------
// GEMM2 via mma.sync bf16 HMMA (proven R12): relu(agg+b1) @ W2 -> bf16.
// ---------------------------------------------------------------------------
#define G2_XSTRIDE 72

__global__ __launch_bounds__(256)
void k_gemm2_mma(const float* __restrict__ X, const float* __restrict__ W,
                 const float* __restrict__ bias, unsigned* __restrict__ out,
                 int N) {
    __shared__ __nv_bfloat16 Xs[128 * G2_XSTRIDE];   // 18432 B
    __shared__ uint2 Wf[4 * 8 * 32];                 // 8192 B

    int tid = threadIdx.x;
    int wid = tid >> 5, lane = tid & 31;
    int tig = lane & 3, gid = lane >> 2;
    int row0 = blockIdx.x * 128;

    for (int idx = tid; idx < 1024; idx += 256) {
        int l = idx & 31;
        int nt = (idx >> 5) & 7;
        int ks = idx >> 8;
        int lt = l & 3, lg = l >> 2;
        int k0 = ks * 16 + lt * 2;
        int n  = nt * 8 + lg;
        float b0 = W[(long long)k0 * 64 + n];
        float b1 = W[(long long)(k0 + 1) * 64 + n];
        float b2 = W[(long long)(k0 + 8) * 64 + n];
        float b3 = W[(long long)(k0 + 9) * 64 + n];
        __nv_bfloat162 p0 = __float22bfloat162_rn(make_float2(b0, b1));
        __nv_bfloat162 p1 = __float22bfloat162_rn(make_float2(b2, b3));
        Wf[idx] = make_uint2(*(unsigned*)&p0, *(unsigned*)&p1);
    }

    for (int idx = tid; idx < 128 * 16; idx += 256) {
        int r  = idx >> 4;
        int c4 = idx & 15;
        int gr = row0 + r;
        float4 v = make_float4(0.f, 0.f, 0.f, 0.f);
        if (gr < N) {
            v = *(const float4*)(X + (long long)gr * 64 + c4 * 4);
            float4 bv = __ldg((const float4*)bias + c4);
            v.x = fmaxf(v.x + bv.x, 0.f);
            v.y = fmaxf(v.y + bv.y, 0.f);
            v.z = fmaxf(v.z + bv.z, 0.f);
            v.w = fmaxf(v.w + bv.w, 0.f);
        }
        __nv_bfloat162 p0 = __float22bfloat162_rn(make_float2(v.x, v.y));
        __nv_bfloat162 p1 = __float22bfloat162_rn(make_float2(v.z, v.w));
        *(uint2*)((char*)Xs + ((long long)r * G2_XSTRIDE + c4 * 4) * 2) =
            make_uint2(*(unsigned*)&p0, *(unsigned*)&p1);
    }
    __syncthreads();

    float acc[8][4];
    #pragma unroll
    for (int nt = 0; nt < 8; nt++)
        #pragma unroll
        for (int q = 0; q < 4; q++) acc[nt][q] = 0.f;

    int rw = wid * 16;
    const char* XsB = (const char*)Xs;

    #pragma unroll
    for (int ks = 0; ks < 4; ks++) {
        int cbase = ks * 16 + tig * 2;
        unsigned A0 = *(const unsigned*)(XsB + ((rw + gid)     * G2_XSTRIDE + cbase)     * 2);
        unsigned A1 = *(const unsigned*)(XsB + ((rw + gid + 8) * G2_XSTRIDE + cbase)     * 2);
        unsigned A2 = *(const unsigned*)(XsB + ((rw + gid)     * G2_XSTRIDE + cbase + 8) * 2);
        unsigned A3 = *(const unsigned*)(XsB + ((rw + gid + 8) * G2_XSTRIDE + cbase + 8) * 2);
        #pragma unroll
        for (int nt = 0; nt < 8; nt++) {
            uint2 bb = Wf[(ks * 8 + nt) * 32 + lane];
            asm volatile(
                "mma.sync.aligned.m16n8k16.row.col.f32.bf16.bf16.f32 "
                "{%0,%1,%2,%3}, {%4,%5,%6,%7}, {%8,%9}, {%0,%1,%2,%3};"
                : "+f"(acc[nt][0]), "+f"(acc[nt][1]),
                  "+f"(acc[nt][2]), "+f"(acc[nt][3])
                : "r"(A0), "r"(A1), "r"(A2), "r"(A3),
                  "r"(bb.x), "r"(bb.y));
        }
    }

    int gr0 = row0 + rw + gid;
    int gr1 = gr0 + 8;
    #pragma unroll
    for (int nt = 0; nt < 8; nt++) {
        int cw = nt * 4 + tig;
        if (gr0 < N) {
            __nv_bfloat162 p = __float22bfloat162_rn(
                make_float2(acc[nt][0], acc[nt][1]));
            out[(long long)gr0 * 32 + cw] = *(unsigned*)&p;
        }
        if (gr1 < N) {
            __nv_bfloat162 p = __float22bfloat162_rn(
                make_float2(acc[nt][2], acc[nt][3]));
            out[(long long)gr1 * 32 + cw] = *(unsigned*)&p;
        }
    }
}

// ---------------------------------------------------------------------------
// Aggregate from bf16 h (pipelined, proven-neutral R13). Warp per node;
// 4 groups of 8 lanes. EPI==1: fuse +b2 and log_softmax.
// ---------------------------------------------------------------------------
template <int EPI>
__global__ void k_agg(const uint4* __restrict__ h, float* __restrict__ out,
                      const float* __restrict__ bias, int N) {
    int node = blockIdx.x * 8 + (threadIdx.x >> 5);
    if (node >= N) return;
    int lane = threadIdx.x & 31;
    int grp = lane >> 3;
    int gl  = lane & 7;
    int beg = g_off[node];
    int end = g_off[node + 1];

    float2 acc[4];
    #pragma unroll
    for (int i = 0; i < 4; i++) acc[i] = make_float2(0.f, 0.f);

    int j = beg + grp;
    float2 r0 = (j < end)     ? __ldg(&g_rec[j])     : make_float2(__int_as_float(0), 0.f);
    float2 r1 = (j + 4 < end) ? __ldg(&g_rec[j + 4]) : make_float2(__int_as_float(0), 0.f);

    #pragma unroll 2
    for (; j < end; j += 4) {
        float2 rn = (j + 8 < end) ? __ldg(&g_rec[j + 8])
                                  : make_float2(__int_as_float(0), 0.f);
        int s = __float_as_int(r0.x);
        float nrm = r0.y;
        uint4 v = __ldg(h + (long long)s * 8 + gl);
        float2 f;
        f = __bfloat1622float2(*(__nv_bfloat162*)&v.x);
        acc[0].x += f.x * nrm; acc[0].y += f.y * nrm;
        f = __bfloat1622float2(*(__nv_bfloat162*)&v.y);
        acc[1].x += f.x * nrm; acc[1].y += f.y * nrm;
        f = __bfloat1622float2(*(__nv_bfloat162*)&v.z);
        acc[2].x += f.x * nrm; acc[2].y += f.y * nrm;
        f = __bfloat1622float2(*(__nv_bfloat162*)&v.w);
        acc[3].x += f.x * nrm; acc[3].y += f.y * nrm;
        r0 = r1;
        r1 = rn;
    }
    #pragma unroll
    for (int i = 0; i < 4; i++) {
        acc[i].x += __shfl_xor_sync(0xffffffffu, acc[i].x, 8);
        acc[i].y += __shfl_xor_sync(0xffffffffu, acc[i].y, 8);
        acc[i].x += __shfl_xor_sync(0xffffffffu, acc[i].x, 16);
        acc[i].y += __shfl_xor_sync(0xffffffffu, acc[i].y, 16);
    }

    if (EPI == 0) {
        if (lane < 8) {
            float4* op = (float4*)(out + (long long)node * 64 + gl * 8);
            op[0] = make_float4(acc[0].x, acc[0].y, acc[1].x, acc[1].y);
            op[1] = make_float4(acc[2].x, acc[2].y, acc[3].x, acc[3].y);
        }
    } else {
        const float4* bp = (const float4*)(bias + gl * 8);
        float4 b0 = bp[0], b1 = bp[1];
        acc[0].x += b0.x; acc[0].y += b0.y; acc[1].x += b0.z; acc[1].y += b0.w;
        acc[2].x += b1.x; acc[2].y += b1.y; acc[3].x += b1.z; acc[3].y += b1.w;
        float m = fmaxf(fmaxf(fmaxf(acc[0].x, acc[0].y), fmaxf(acc[1].x, acc[1].y)),
                        fmaxf(fmaxf(acc[2].x, acc[2].y), fmaxf(acc[3].x, acc[3].y)));
        #pragma unroll
        for (int o = 1; o < 8; o <<= 1)
            m = fmaxf(m, __shfl_xor_sync(0xffffffffu, m, o));
        float s = expf(acc[0].x - m) + expf(acc[0].y - m)
                + expf(acc[1].x - m) + expf(acc[1].y - m)
                + expf(acc[2].x - m) + expf(acc[2].y - m)
                + expf(acc[3].x - m) + expf(acc[3].y - m);
        #pragma unroll
        for (int o = 1; o < 8; o <<= 1)
            s += __shfl_xor_sync(0xffffffffu, s, o);
        float lse = m + logf(s);
        if (lane < 8) {
            float4* op = (float4*)(out + (long long)node * 64 + gl * 8);
            op[0] = make_float4(acc[0].x - lse, acc[0].y - lse,
                                acc[1].x - lse, acc[1].y - lse);
            op[1] = make_float4(acc[2].x - lse, acc[2].y - lse,
                                acc[3].x - lse, acc[3].y - lse);
        }
    }
}

// ---------------------------------------------------------------------------
extern "C" void kernel_launch(void* const* d_in, const int* in_sizes, int n_in,
                              void* d_out, int out_size) {
    const float* x  = (const float*)d_in[0];
    const void*  ei = d_in[1];
    const float* W1 = (const float*)d_in[2];
    const float* b1 = (const float*)d_in[3];
    const float* W2 = (const float*)d_in[4];
    const float* b2 = (const float*)d_in[5];
    float* out = (float*)d_out;

    int N = in_sizes[0] / 128;                 // 100000
    long long E = (long long)in_sizes[1] / 2;  // 1600000
    long long M = E + (long long)N;

    static cudaStream_t s2 = nullptr;
    static cudaEvent_t evFork = nullptr, evJoin = nullptr;
    if (!s2) {
        cudaStreamCreateWithFlags(&s2, cudaStreamNonBlocking);
        cudaEventCreateWithFlags(&evFork, cudaEventDisableTiming);
        cudaEventCreateWithFlags(&evJoin, cudaEventDisableTiming);
        cudaFuncSetAttribute(k_gemm1_mma,
                             cudaFuncAttributeMaxDynamicSharedMemorySize,
                             G1_SMEM_TOT);
    }

    uint4* ph;
    float* pagg;
    cudaGetSymbolAddress((void**)&ph, g_h);
    cudaGetSymbolAddress((void**)&pagg, g_agg);

    int bN    = (N + 255) / 256;
    int bDeg  = (int)((E + 255) / 256);
    int bMsg  = (int)((M + 255) / 256);
    int bGemm = (N + 127) / 128;
    int bAgg  = (N + 7) / 8;

    // Fork: HMMA GEMM1 (x,W1 only) on s2, concurrent with CSR prep.
    cudaEventRecord(evFork, 0);
    cudaStreamWaitEvent(s2, evFork, 0);
    k_gemm1_mma<<<bGemm, 256, G1_SMEM_TOT, s2>>>(x, W1, (unsigned*)ph, N);
    cudaEventRecord(evJoin, s2);

    k_init<<<bN, 256>>>(ei, N);
    k_count<<<bDeg, 256>>>(ei, E);
    k_scan1<<<bN, 256>>>(N);
    k_scan23<<<bN, 256>>>(N, bN);
    k_place<<<bMsg, 256>>>(ei, E, N);

    // Join: aggregation needs both g_h (s2) and g_rec (default)
    cudaStreamWaitEvent(0, evJoin, 0);

    // layer 1 aggregate (fp32 out)
    k_agg<0><<<bAgg, 256>>>(ph, pagg, nullptr, N);

    // layer 2: h2 = relu(agg1 + b1) @ W2 via HMMA (bf16 out, overwrites g_h)
    k_gemm2_mma<<<bGemm, 256>>>(pagg, W2, b1, (unsigned*)ph, N);

    // final aggregate + b2 + log_softmax
    k_agg<1><<<bAgg, 256>>>(ph, out, b2, N);
}

// round 15
// speedup vs baseline: 1.0127x; 1.0056x over previous
#include <cuda_runtime.h>
#include <cuda_bf16.h>
#include <math.h>
#include <stdint.h>

// Fixed problem shape (from setup_inputs): N=100000, E=1600000, F_IN=128, H=C=64
#define NNODES 100000
#define HD 64
#define MSGMAX 1800000   // E + N with headroom

// Scratch (allocation-free: __device__ globals)
__device__ int    g_cnt[NNODES];            // per-dst message count (incl. self-loop)
__device__ int    g_off[NNODES + 1];        // CSR offsets
__device__ int    g_cur[NNODES];            // placement cursors
__device__ int    g_bsum[512];              // block sums for scan
__device__ float2 g_rec[MSGMAX];            // per-message {src_bits, norm}
__device__ uint4  g_h[NNODES * 8];          // bf16 h1 (gemm1 out / agg0 in), then h2
__device__ uint4  g_hb[NNODES * 8];         // bf16 relu(agg0+b1) (agg0 out / gemm2 in)
__device__ int    g_is64;                   // edge_index dtype flag

__device__ __forceinline__ long long load_edge(const void* ei, long long pos) {
    if (g_is64) return ((const long long*)ei)[pos];
    return (long long)((const int*)ei)[pos];
}

// ---------------------------------------------------------------------------
// init: cnt = 1 (self loop), detect index width
// ---------------------------------------------------------------------------
__global__ void k_init(const void* ei, int N) {
    int i = blockIdx.x * 256 + threadIdx.x;
    if (i < N) g_cnt[i] = 1;
    if (i == 0) {
        const unsigned long long* p = (const unsigned long long*)ei;
        int ok = 1;
        #pragma unroll 4
        for (int j = 0; j < 64; j++)
            if (p[j] >= (unsigned long long)N) ok = 0;
        g_is64 = ok;
    }
}

// ---------------------------------------------------------------------------
// degree count over dst
// ---------------------------------------------------------------------------
__global__ void k_count(const void* ei, long long E) {
    long long e = (long long)blockIdx.x * 256 + threadIdx.x;
    if (e < E) {
        int d = (int)load_edge(ei, E + e);
        atomicAdd(&g_cnt[d], 1);
    }
}

// ---------------------------------------------------------------------------
// scan stage (2 kernels, shuffle-based; proven R14)
// ---------------------------------------------------------------------------
__global__ void k_scan1(int N) {
    __shared__ int ws[8];
    int i = blockIdx.x * 256 + threadIdx.x;
    int lane = threadIdx.x & 31;
    int w = threadIdx.x >> 5;
    int v = (i < N) ? g_cnt[i] : 0;
    int s = v;
    #pragma unroll
    for (int o = 16; o > 0; o >>= 1) s += __shfl_xor_sync(0xffffffffu, s, o);
    if (lane == 0) ws[w] = s;
    __syncthreads();
    if (threadIdx.x < 8) {
        int t = ws[threadIdx.x];
        #pragma unroll
        for (int o = 4; o > 0; o >>= 1) t += __shfl_xor_sync(0xffu, t, o);
        if (threadIdx.x == 0) g_bsum[blockIdx.x] = t;
    }
}

__global__ void k_scan23(int N, int nb) {
    __shared__ int wsum[8];
    __shared__ int bws[8];
    int b = blockIdx.x, tid = threadIdx.x;
    int lane = tid & 31;
    int w = tid >> 5;
    int i = b * 256 + tid;

    int part = 0;
    for (int j = tid; j < b; j += 256) part += g_bsum[j];
    #pragma unroll
    for (int o = 16; o > 0; o >>= 1) part += __shfl_xor_sync(0xffffffffu, part, o);
    if (lane == 0) bws[w] = part;

    int v = (i < N) ? g_cnt[i] : 0;
    int x = v;
    #pragma unroll
    for (int o = 1; o < 32; o <<= 1) {
        int y = __shfl_up_sync(0xffffffffu, x, o);
        if (lane >= o) x += y;
    }
    if (lane == 31) wsum[w] = x;
    __syncthreads();

    int blockoff = 0;
    #pragma unroll
    for (int q = 0; q < 8; q++) blockoff += bws[q];
    int wbase = 0;
    #pragma unroll
    for (int q = 0; q < 8; q++) wbase += (q < w) ? wsum[q] : 0;

    if (i < N) {
        int off = blockoff + wbase + x - v;   // exclusive
        g_off[i] = off;
        g_cur[i] = off;
        if (i == N - 1) g_off[N] = off + v;
    }
}

// ---------------------------------------------------------------------------
// place: bucket message records {src, rsqrt(deg_s*deg_d)} by dst
// ---------------------------------------------------------------------------
__global__ void k_place(const void* ei, long long E, int N) {
    long long e = (long long)blockIdx.x * 256 + threadIdx.x;
    long long M = E + (long long)N;
    if (e >= M) return;
    int s, d;
    if (e < E) {
        s = (int)load_edge(ei, e);
        d = (int)load_edge(ei, E + e);
    } else {
        s = d = (int)(e - E);
    }
    float nrm = rsqrtf((float)(g_cnt[s] * g_cnt[d]));
    int pos = atomicAdd(&g_cur[d], 1);
    g_rec[pos] = make_float2(__int_as_float(s), nrm);
}

// ---------------------------------------------------------------------------
// GEMM1 via mma.sync bf16 HMMA (proven R11).
// ---------------------------------------------------------------------------
#define G1_XSTRIDE 136
#define G1_XS_BYTES (128 * G1_XSTRIDE * 2)
#define G1_WF_OFF   G1_XS_BYTES
#define G1_SMEM_TOT (G1_XS_BYTES + 8 * 8 * 32 * 8)

__global__ __launch_bounds__(256)
void k_gemm1_mma(const float* __restrict__ X, const float* __restrict__ W,
                 unsigned* __restrict__ out, int N) {
    extern __shared__ char smem[];
    __nv_bfloat16* Xs = (__nv_bfloat16*)smem;
    uint2* Wf = (uint2*)(smem + G1_WF_OFF);

    int tid = threadIdx.x;
    int wid = tid >> 5, lane = tid & 31;
    int tig = lane & 3, gid = lane >> 2;
    int row0 = blockIdx.x * 128;

    for (int idx = tid; idx < 2048; idx += 256) {
        int l = idx & 31;
        int nt = (idx >> 5) & 7;
        int ks = idx >> 8;
        int lt = l & 3, lg = l >> 2;
        int k0 = ks * 16 + lt * 2;
        int n  = nt * 8 + lg;
        float b0 = W[(long long)k0 * 64 + n];
        float b1 = W[(long long)(k0 + 1) * 64 + n];
        float b2 = W[(long long)(k0 + 8) * 64 + n];
        float b3 = W[(long long)(k0 + 9) * 64 + n];
        __nv_bfloat162 p0 = __float22bfloat162_rn(make_float2(b0, b1));
        __nv_bfloat162 p1 = __float22bfloat162_rn(make_float2(b2, b3));
        Wf[idx] = make_uint2(*(unsigned*)&p0, *(unsigned*)&p1);
    }

    for (int idx = tid; idx < 128 * 32; idx += 256) {
        int r  = idx >> 5;
        int c4 = idx & 31;
        int gr = row0 + r;
        float4 v = make_float4(0.f, 0.f, 0.f, 0.f);
        if (gr < N) v = *(const float4*)(X + (long long)gr * 128 + c4 * 4);
        __nv_bfloat162 p0 = __float22bfloat162_rn(make_float2(v.x, v.y));
        __nv_bfloat162 p1 = __float22bfloat162_rn(make_float2(v.z, v.w));
        *(uint2*)((char*)Xs + ((long long)r * G1_XSTRIDE + c4 * 4) * 2) =
            make_uint2(*(unsigned*)&p0, *(unsigned*)&p1);
    }
    __syncthreads();

    float acc[8][4];
    #pragma unroll
    for (int nt = 0; nt < 8; nt++)
        #pragma unroll
        for (int q = 0; q < 4; q++) acc[nt][q] = 0.f;

    int rw = wid * 16;
    const char* XsB = (const char*)Xs;

    #pragma unroll
    for (int ks = 0; ks < 8; ks++) {
        int cbase = ks * 16 + tig * 2;
        unsigned A0 = *(const unsigned*)(XsB + ((rw + gid)     * G1_XSTRIDE + cbase)     * 2);
        unsigned A1 = *(const unsigned*)(XsB + ((rw + gid + 8) * G1_XSTRIDE + cbase)     * 2);
        unsigned A2 = *(const unsigned*)(XsB + ((rw + gid)     * G1_XSTRIDE + cbase + 8) * 2);
        unsigned A3 = *(const unsigned*)(XsB + ((rw + gid + 8) * G1_XSTRIDE + cbase + 8) * 2);
        #pragma unroll
        for (int nt = 0; nt < 8; nt++) {
            uint2 bb = Wf[(ks * 8 + nt) * 32 + lane];
            asm volatile(
                "mma.sync.aligned.m16n8k16.row.col.f32.bf16.bf16.f32 "
                "{%0,%1,%2,%3}, {%4,%5,%6,%7}, {%8,%9}, {%0,%1,%2,%3};"
                : "+f"(acc[nt][0]), "+f"(acc[nt][1]),
                  "+f"(acc[nt][2]), "+f"(acc[nt][3])
                : "r"(A0), "r"(A1), "r"(A2), "r"(A3),
                  "r"(bb.x), "r"(bb.y));
        }
    }

    int gr0 = row0 + rw + gid;
    int gr1 = gr0 + 8;
    #pragma unroll
    for (int nt = 0; nt < 8; nt++) {
        int cw = nt * 4 + tig;
        if (gr0 < N) {
            __nv_bfloat162 p = __float22bfloat162_rn(
                make_float2(acc[nt][0], acc[nt][1]));
            out[(long long)gr0 * 32 + cw] = *(unsigned*)&p;
        }
        if (gr1 < N) {
            __nv_bfloat162 p = __float22bfloat162_rn(
                make_float2(acc[nt][2], acc[nt][3]));
            out[(long long)gr1 * 32 + cw] = *(unsigned*)&p;
        }
    }
}

// ---------------------------------------------------------------------------
// GEMM2 via mma.sync bf16 HMMA: h2[N,64](bf16) = Xb[N,64](bf16) @ W2.
// Input already has b1+relu applied (folded into agg0). X-load is a pure
// uint4 copy (no convert, no bias).
// ---------------------------------------------------------------------------
#define G2_XSTRIDE 72

__global__ __launch_bounds__(256)
void k_gemm2_mma(const uint4* __restrict__ Xb, const float* __restrict__ W,
                 unsigned* __restrict__ out, int N) {
    __shared__ __nv_bfloat16 Xs[128 * G2_XSTRIDE];   // 18432 B
    __shared__ uint2 Wf[4 * 8 * 32];                 // 8192 B

    int tid = threadIdx.x;
    int wid = tid >> 5, lane = tid & 31;
    int tig = lane & 3, gid = lane >> 2;
    int row0 = blockIdx.x * 128;

    for (int idx = tid; idx < 1024; idx += 256) {
        int l = idx & 31;
        int nt = (idx >> 5) & 7;
        int ks = idx >> 8;
        int lt = l & 3, lg = l >> 2;
        int k0 = ks * 16 + lt * 2;
        int n  = nt * 8 + lg;
        float b0 = W[(long long)k0 * 64 + n];
        float b1 = W[(long long)(k0 + 1) * 64 + n];
        float b2 = W[(long long)(k0 + 8) * 64 + n];
        float b3 = W[(long long)(k0 + 9) * 64 + n];
        __nv_bfloat162 p0 = __float22bfloat162_rn(make_float2(b0, b1));
        __nv_bfloat162 p1 = __float22bfloat162_rn(make_float2(b2, b3));
        Wf[idx] = make_uint2(*(unsigned*)&p0, *(unsigned*)&p1);
    }

    // X tile: direct bf16 copy, 128 rows x 8 uint4
    for (int idx = tid; idx < 128 * 8; idx += 256) {
        int r = idx >> 3;
        int c = idx & 7;
        int gr = row0 + r;
        uint4 v = make_uint4(0u, 0u, 0u, 0u);
        if (gr < N) v = __ldg(Xb + (long long)gr * 8 + c);
        *(uint4*)((char*)Xs + r * (G2_XSTRIDE * 2) + c * 16) = v;
    }
    __syncthreads();

    float acc[8][4];
    #pragma unroll
    for (int nt = 0; nt < 8; nt++)
        #pragma unroll
        for (int q = 0; q < 4; q++) acc[nt][q] = 0.f;

    int rw = wid * 16;
    const char* XsB = (const char*)Xs;

    #pragma unroll
    for (int ks = 0; ks < 4; ks++) {
        int cbase = ks * 16 + tig * 2;
        unsigned A0 = *(const unsigned*)(XsB + ((rw + gid)     * G2_XSTRIDE + cbase)     * 2);
        unsigned A1 = *(const unsigned*)(XsB + ((rw + gid + 8) * G2_XSTRIDE + cbase)     * 2);
        unsigned A2 = *(const unsigned*)(XsB + ((rw + gid)     * G2_XSTRIDE + cbase + 8) * 2);
        unsigned A3 = *(const unsigned*)(XsB + ((rw + gid + 8) * G2_XSTRIDE + cbase + 8) * 2);
        #pragma unroll
        for (int nt = 0; nt < 8; nt++) {
            uint2 bb = Wf[(ks * 8 + nt) * 32 + lane];
            asm volatile(
                "mma.sync.aligned.m16n8k16.row.col.f32.bf16.bf16.f32 "
                "{%0,%1,%2,%3}, {%4,%5,%6,%7}, {%8,%9}, {%0,%1,%2,%3};"
                : "+f"(acc[nt][0]), "+f"(acc[nt][1]),
                  "+f"(acc[nt][2]), "+f"(acc[nt][3])
                : "r"(A0), "r"(A1), "r"(A2), "r"(A3),
                  "r"(bb.x), "r"(bb.y));
        }
    }

    int gr0 = row0 + rw + gid;
    int gr1 = gr0 + 8;
    #pragma unroll
    for (int nt = 0; nt < 8; nt++) {
        int cw = nt * 4 + tig;
        if (gr0 < N) {
            __nv_bfloat162 p = __float22bfloat162_rn(
                make_float2(acc[nt][0], acc[nt][1]));
            out[(long long)gr0 * 32 + cw] = *(unsigned*)&p;
        }
        if (gr1 < N) {
            __nv_bfloat162 p = __float22bfloat162_rn(
                make_float2(acc[nt][2], acc[nt][3]));
            out[(long long)gr1 * 32 + cw] = *(unsigned*)&p;
        }
    }
}

// ---------------------------------------------------------------------------
// Aggregate from bf16 h (pipelined). Warp per node; 4 groups of 8 lanes.
// EPI==0: +b1, relu, write bf16 uint4 (GEMM2 input).
// EPI==1: +b2, log_softmax, write fp32 output.
// ---------------------------------------------------------------------------
template <int EPI>
__global__ void k_agg(const uint4* __restrict__ h, void* __restrict__ outp,
                      const float* __restrict__ bias, int N) {
    int node = blockIdx.x * 8 + (threadIdx.x >> 5);
    if (node >= N) return;
    int lane = threadIdx.x & 31;
    int grp = lane >> 3;
    int gl  = lane & 7;
    int beg = g_off[node];
    int end = g_off[node + 1];

    float2 acc[4];
    #pragma unroll
    for (int i = 0; i < 4; i++) acc[i] = make_float2(0.f, 0.f);

    int j = beg + grp;
    float2 r0 = (j < end)     ? __ldg(&g_rec[j])     : make_float2(__int_as_float(0), 0.f);
    float2 r1 = (j + 4 < end) ? __ldg(&g_rec[j + 4]) : make_float2(__int_as_float(0), 0.f);

    #pragma unroll 2
    for (; j < end; j += 4) {
        float2 rn = (j + 8 < end) ? __ldg(&g_rec[j + 8])
                                  : make_float2(__int_as_float(0), 0.f);
        int s = __float_as_int(r0.x);
        float nrm = r0.y;
        uint4 v = __ldg(h + (long long)s * 8 + gl);
        float2 f;
        f = __bfloat1622float2(*(__nv_bfloat162*)&v.x);
        acc[0].x += f.x * nrm; acc[0].y += f.y * nrm;
        f = __bfloat1622float2(*(__nv_bfloat162*)&v.y);
        acc[1].x += f.x * nrm; acc[1].y += f.y * nrm;
        f = __bfloat1622float2(*(__nv_bfloat162*)&v.z);
        acc[2].x += f.x * nrm; acc[2].y += f.y * nrm;
        f = __bfloat1622float2(*(__nv_bfloat162*)&v.w);
        acc[3].x += f.x * nrm; acc[3].y += f.y * nrm;
        r0 = r1;
        r1 = rn;
    }
    #pragma unroll
    for (int i = 0; i < 4; i++) {
        acc[i].x += __shfl_xor_sync(0xffffffffu, acc[i].x, 8);
        acc[i].y += __shfl_xor_sync(0xffffffffu, acc[i].y, 8);
        acc[i].x += __shfl_xor_sync(0xffffffffu, acc[i].x, 16);
        acc[i].y += __shfl_xor_sync(0xffffffffu, acc[i].y, 16);
    }

    const float4* bp = (const float4*)(bias + gl * 8);
    float4 b0 = bp[0], b1 = bp[1];
    acc[0].x += b0.x; acc[0].y += b0.y; acc[1].x += b0.z; acc[1].y += b0.w;
    acc[2].x += b1.x; acc[2].y += b1.y; acc[3].x += b1.z; acc[3].y += b1.w;

    if (EPI == 0) {
        if (lane < 8) {
            #pragma unroll
            for (int i = 0; i < 4; i++) {
                acc[i].x = fmaxf(acc[i].x, 0.f);
                acc[i].y = fmaxf(acc[i].y, 0.f);
            }
            __nv_bfloat162 p0 = __float22bfloat162_rn(acc[0]);
            __nv_bfloat162 p1 = __float22bfloat162_rn(acc[1]);
            __nv_bfloat162 p2 = __float22bfloat162_rn(acc[2]);
            __nv_bfloat162 p3 = __float22bfloat162_rn(acc[3]);
            uint4 pk;
            pk.x = *(unsigned*)&p0; pk.y = *(unsigned*)&p1;
            pk.z = *(unsigned*)&p2; pk.w = *(unsigned*)&p3;
            ((uint4*)outp)[(long long)node * 8 + gl] = pk;
        }
    } else {
        float m = fmaxf(fmaxf(fmaxf(acc[0].x, acc[0].y), fmaxf(acc[1].x, acc[1].y)),
                        fmaxf(fmaxf(acc[2].x, acc[2].y), fmaxf(acc[3].x, acc[3].y)));
        #pragma unroll
        for (int o = 1; o < 8; o <<= 1)
            m = fmaxf(m, __shfl_xor_sync(0xffffffffu, m, o));
        float s = expf(acc[0].x - m) + expf(acc[0].y - m)
                + expf(acc[1].x - m) + expf(acc[1].y - m)
                + expf(acc[2].x - m) + expf(acc[2].y - m)
                + expf(acc[3].x - m) + expf(acc[3].y - m);
        #pragma unroll
        for (int o = 1; o < 8; o <<= 1)
            s += __shfl_xor_sync(0xffffffffu, s, o);
        float lse = m + logf(s);
        if (lane < 8) {
            float* out = (float*)outp;
            float4* op = (float4*)(out + (long long)node * 64 + gl * 8);
            op[0] = make_float4(acc[0].x - lse, acc[0].y - lse,
                                acc[1].x - lse, acc[1].y - lse);
            op[1] = make_float4(acc[2].x - lse, acc[2].y - lse,
                                acc[3].x - lse, acc[3].y - lse);
        }
    }
}

// ---------------------------------------------------------------------------
extern "C" void kernel_launch(void* const* d_in, const int* in_sizes, int n_in,
                              void* d_out, int out_size) {
    const float* x  = (const float*)d_in[0];
    const void*  ei = d_in[1];
    const float* W1 = (const float*)d_in[2];
    const float* b1 = (const float*)d_in[3];
    const float* W2 = (const float*)d_in[4];
    const float* b2 = (const float*)d_in[5];
    float* out = (float*)d_out;

    int N = in_sizes[0] / 128;                 // 100000
    long long E = (long long)in_sizes[1] / 2;  // 1600000
    long long M = E + (long long)N;

    static cudaStream_t s2 = nullptr;
    static cudaEvent_t evFork = nullptr, evJoin = nullptr;
    if (!s2) {
        cudaStreamCreateWithFlags(&s2, cudaStreamNonBlocking);
        cudaEventCreateWithFlags(&evFork, cudaEventDisableTiming);
        cudaEventCreateWithFlags(&evJoin, cudaEventDisableTiming);
        cudaFuncSetAttribute(k_gemm1_mma,
                             cudaFuncAttributeMaxDynamicSharedMemorySize,
                             G1_SMEM_TOT);
    }

    uint4 *ph, *phb;
    cudaGetSymbolAddress((void**)&ph, g_h);
    cudaGetSymbolAddress((void**)&phb, g_hb);

    int bN    = (N + 255) / 256;
    int bDeg  = (int)((E + 255) / 256);
    int bMsg  = (int)((M + 255) / 256);
    int bGemm = (N + 127) / 128;
    int bAgg  = (N + 7) / 8;

    // Fork: HMMA GEMM1 (x,W1 only) on s2, concurrent with CSR prep.
    cudaEventRecord(evFork, 0);
    cudaStreamWaitEvent(s2, evFork, 0);
    k_gemm1_mma<<<bGemm, 256, G1_SMEM_TOT, s2>>>(x, W1, (unsigned*)ph, N);
    cudaEventRecord(evJoin, s2);

    k_init<<<bN, 256>>>(ei, N);
    k_count<<<bDeg, 256>>>(ei, E);
    k_scan1<<<bN, 256>>>(N);
    k_scan23<<<bN, 256>>>(N, bN);
    k_place<<<bMsg, 256>>>(ei, E, N);

    // Join: aggregation needs both g_h (s2) and g_rec (default)
    cudaStreamWaitEvent(0, evJoin, 0);

    // layer-1 aggregate + b1 + relu -> bf16 g_hb
    k_agg<0><<<bAgg, 256>>>(ph, phb, b1, N);

    // layer 2: h2 = g_hb @ W2 via HMMA (bf16 in/out; writes g_h, agg0 done)
    k_gemm2_mma<<<bGemm, 256>>>(phb, W2, (unsigned*)ph, N);

    // final aggregate + b2 + log_softmax
    k_agg<1><<<bAgg, 256>>>(ph, out, b2, N);
}